// round 5
// baseline (speedup 1.0000x reference)
#include <cuda_runtime.h>
#include <math.h>

#define BQ    1024
#define NM    50000
#define DD    256
#define MAXA  200
#define KSEL  8
#define NSPLIT 37
#define SPLEN  1352            // ceil(50000/37)
#define NCAND (NSPLIT*KSEL)    // 296
#define BIGF  3.0e38f

// -------- device scratch --------
__device__ float g_mem_hyp[NM * DD];
__device__ float g_mem_sq[NM];
__device__ float g_q_hyp[BQ * DD];
__device__ float g_q_sq[BQ];
__device__ float g_cand_arg[BQ * NCAND];
__device__ int   g_cand_idx[BQ * NCAND];

// -------- packed f32x2 helpers (transform kernel) --------
__device__ __forceinline__ unsigned long long dup2(float x) {
    unsigned long long r;
    asm("mov.b64 %0, {%1, %1};" : "=l"(r) : "f"(x));
    return r;
}
__device__ __forceinline__ void ffma2(unsigned long long& d,
                                      unsigned long long a, unsigned long long b) {
    asm("fma.rn.f32x2 %0, %1, %2, %0;" : "+l"(d) : "l"(a), "l"(b));
}
__device__ __forceinline__ float2 unpack2(unsigned long long v) {
    float2 r;
    asm("mov.b64 {%0, %1}, %2;" : "=f"(r.x), "=f"(r.y) : "l"(v));
    return r;
}

// -------- tf32 helpers --------
__device__ __forceinline__ unsigned cvt_tf32(float x) {
    unsigned r;
    asm("cvt.rna.tf32.f32 %0, %1;" : "=r"(r) : "f"(x));
    return r;
}
__device__ __forceinline__ void mma_tf32(float& d0, float& d1, float& d2, float& d3,
                                         unsigned a0, unsigned a1, unsigned a2, unsigned a3,
                                         unsigned b0, unsigned b1) {
    asm("mma.sync.aligned.m16n8k8.row.col.f32.tf32.tf32.f32 "
        "{%0,%1,%2,%3}, {%4,%5,%6,%7}, {%8,%9}, {%0,%1,%2,%3};"
        : "+f"(d0), "+f"(d1), "+f"(d2), "+f"(d3)
        : "r"(a0), "r"(a1), "r"(a2), "r"(a3), "r"(b0), "r"(b1));
}

// ============================================================
// Kernel 1: H = tanh(X@W + b), Poincare rescale, row |h|^2 (unchanged)
// ============================================================
__global__ __launch_bounds__(256, 2)
void transform_kernel(const float* __restrict__ X, const float* __restrict__ W,
                      const float* __restrict__ bias,
                      float* __restrict__ H, float* __restrict__ SQ, int M)
{
    __shared__ float  Xs[64][17];
    __shared__ float2 Ws2[16][128];
    __shared__ float  s_scale[64];

    const int tid = threadIdx.x;
    const int tx = tid & 15, ty = tid >> 4;
    const int row0 = blockIdx.x * 64;

    unsigned long long acc2[4][8];
#pragma unroll
    for (int i = 0; i < 4; i++)
#pragma unroll
        for (int j = 0; j < 8; j++) acc2[i][j] = 0ull;

    for (int kc = 0; kc < DD; kc += 16) {
#pragma unroll
        for (int e = tid; e < 64 * 16; e += 256) {
            int r = e >> 4, k = e & 15;
            float v = 0.f;
            if (row0 + r < M) v = X[(row0 + r) * DD + kc + k];
            Xs[r][k] = v;
        }
#pragma unroll
        for (int e = tid; e < 16 * 256; e += 256) {
            int k = e >> 8, c = e & 255;
            ((float*)Ws2)[k * 256 + c] = W[(kc + k) * DD + c];
        }
        __syncthreads();
#pragma unroll
        for (int k = 0; k < 16; k++) {
            unsigned long long a2[4], b2[8];
#pragma unroll
            for (int i = 0; i < 4; i++) a2[i] = dup2(Xs[ty + 16 * i][k]);
#pragma unroll
            for (int j = 0; j < 8; j++) {
                float2 bv = Ws2[k][tx + 16 * j];
                b2[j] = *(unsigned long long*)&bv;
            }
#pragma unroll
            for (int i = 0; i < 4; i++)
#pragma unroll
                for (int j = 0; j < 8; j++)
                    ffma2(acc2[i][j], a2[i], b2[j]);
        }
        __syncthreads();
    }

    const float2* bias2 = (const float2*)bias;
    float2 hv[4][8];
    float psum[4];
#pragma unroll
    for (int i = 0; i < 4; i++) {
        psum[i] = 0.f;
#pragma unroll
        for (int j = 0; j < 8; j++) {
            float2 bb = bias2[tx + 16 * j];
            float2 v = unpack2(acc2[i][j]);
            v.x = tanhf(v.x + bb.x);
            v.y = tanhf(v.y + bb.y);
            hv[i][j] = v;
            psum[i] += v.x * v.x + v.y * v.y;
        }
    }
#pragma unroll
    for (int off = 1; off < 16; off <<= 1) {
#pragma unroll
        for (int i = 0; i < 4; i++)
            psum[i] += __shfl_xor_sync(0xffffffffu, psum[i], off);
    }
    if (tx == 0) {
#pragma unroll
        for (int i = 0; i < 4; i++) {
            int r = ty + 16 * i;
            float norm = sqrtf(psum[i]);
            float sc = (norm > 0.95f) ? 0.95f / norm : 1.0f;
            s_scale[r] = sc;
            if (row0 + r < M) SQ[row0 + r] = psum[i] * sc * sc;
        }
    }
    __syncthreads();
    float2* H2 = (float2*)H;
#pragma unroll
    for (int i = 0; i < 4; i++) {
        int r = ty + 16 * i;
        if (row0 + r >= M) continue;
        float sc = s_scale[r];
#pragma unroll
        for (int j = 0; j < 8; j++) {
            float2 v = hv[i][j];
            v.x *= sc; v.y *= sc;
            H2[(size_t)(row0 + r) * 128 + tx + 16 * j] = v;
        }
    }
}

// ============================================================
// Kernel 2: tf32 mma.sync split-precision dist GEMM + arg + top-8/split.
// CTA 128q x 64m, 8 warps (warp = 32q x 32m), BK=16 (2 k-steps per fill).
// smem k-permuted hi/lo pack: one LDS.128 = (hi_k, lo_k, hi_{k+4}, lo_{k+4}).
// dot = hi*hi + hi*lo + lo*hi  (error ~2^-22, selection-exact).
// ============================================================
#define QROW 36          // floats per q row (32 data + pad)
#define ABROW 72         // argbuf row stride (conflict-free STS.64/LDS.128)

struct __align__(16) DistSmem {
    union {
        struct {
            float QS[128][QROW];
            float MS[64][QROW];
        } g;
        float argbuf[128][ABROW];
    } u;
    float ys[64];
    float s_ta[128][KSEL];
    int   s_ti[128][KSEL];
};

__global__ __launch_bounds__(256, 2)
void dist_topk_kernel()
{
    __shared__ DistSmem sm;

    const int tid = threadIdx.x;
    const int lane = tid & 31;
    const int wid = tid >> 5;
    const int warp_q = wid & 3;          // 4 q-warps * 32 = 128
    const int warp_m = wid >> 2;         // 2 m-warps * 32 = 64
    const int g4 = lane >> 2;            // groupID 0..7
    const int tg = lane & 3;             // thread-in-group

    const int q0 = blockIdx.x * 128;
    const int mstart = blockIdx.y * SPLEN;
    const int mend = min(mstart + SPLEN, NM);

    // per-thread query stats: q = warp_q*32 + i*16 + r*8 + g4
    float xs[2][2], inv1x[2][2];
#pragma unroll
    for (int i = 0; i < 2; i++)
#pragma unroll
        for (int r = 0; r < 2; r++) {
            float v = g_q_sq[q0 + warp_q * 32 + i * 16 + r * 8 + g4];
            xs[i][r] = v;
            inv1x[i][r] = 1.0f - v;
        }

    if (tid < 128) {
#pragma unroll
        for (int s = 0; s < KSEL; s++) { sm.s_ta[tid][s] = BIGF; sm.s_ti[tid][s] = 0x7fffffff; }
    }
    float worst = BIGF;
    __syncthreads();

    for (int m0 = mstart; m0 < mend; m0 += 64) {
        // ys for this m-block
        if (tid < 64) {
            int m = m0 + tid;
            sm.ys[tid] = (m < mend) ? g_mem_sq[m] : 0.f;
        }

        float acc[2][4][4];
#pragma unroll
        for (int i = 0; i < 2; i++)
#pragma unroll
            for (int j = 0; j < 4; j++)
#pragma unroll
                for (int c = 0; c < 4; c++) acc[i][j][c] = 0.f;

        for (int kc = 0; kc < DD; kc += 16) {
            // ---- fill Q tile: 128 x 16k -> hi/lo permuted ----
#pragma unroll
            for (int it = 0; it < 2; it++) {
                int f = tid + 256 * it;          // 512 float4 total
                int q = f >> 2;
                int kq = (f & 3) * 4;            // 0,4,8,12
                float4 v = *(const float4*)&g_q_hyp[(size_t)(q0 + q) * DD + kc + kq];
                int s = kq >> 3, half = (kq >> 2) & 1;
                int ob = s * 16 + half * 2;
                float vv[4] = {v.x, v.y, v.z, v.w};
#pragma unroll
                for (int e = 0; e < 4; e++) {
                    float hi = __uint_as_float(cvt_tf32(vv[e]));
                    float lo = __uint_as_float(cvt_tf32(vv[e] - hi));
                    sm.u.g.QS[q][ob + e * 4 + 0] = hi;
                    sm.u.g.QS[q][ob + e * 4 + 1] = lo;
                }
            }
            // ---- fill M tile: 64 x 16k ----
            {
                int f = tid;                     // 256 float4
                int row = f >> 2;
                int kq = (f & 3) * 4;
                float4 v = make_float4(0.f, 0.f, 0.f, 0.f);
                if (m0 + row < mend)
                    v = *(const float4*)&g_mem_hyp[(size_t)(m0 + row) * DD + kc + kq];
                int s = kq >> 3, half = (kq >> 2) & 1;
                int ob = s * 16 + half * 2;
                float vv[4] = {v.x, v.y, v.z, v.w};
#pragma unroll
                for (int e = 0; e < 4; e++) {
                    float hi = __uint_as_float(cvt_tf32(vv[e]));
                    float lo = __uint_as_float(cvt_tf32(vv[e] - hi));
                    sm.u.g.MS[row][ob + e * 4 + 0] = hi;
                    sm.u.g.MS[row][ob + e * 4 + 1] = lo;
                }
            }
            __syncthreads();

            // ---- 2 k-steps of mma ----
#pragma unroll
            for (int s = 0; s < 2; s++) {
                const int off = s * 16 + tg * 4;
                // A fragments (i = 0,1): two LDS.128 each
                unsigned ah[2][4], al[2][4];
#pragma unroll
                for (int i = 0; i < 2; i++) {
                    int qr = warp_q * 32 + i * 16 + g4;
                    float4 p0 = *(const float4*)&sm.u.g.QS[qr][off];      // a0,a2 hi/lo
                    float4 p1 = *(const float4*)&sm.u.g.QS[qr + 8][off];  // a1,a3 hi/lo
                    ah[i][0] = __float_as_uint(p0.x); al[i][0] = __float_as_uint(p0.y);
                    ah[i][2] = __float_as_uint(p0.z); al[i][2] = __float_as_uint(p0.w);
                    ah[i][1] = __float_as_uint(p1.x); al[i][1] = __float_as_uint(p1.y);
                    ah[i][3] = __float_as_uint(p1.z); al[i][3] = __float_as_uint(p1.w);
                }
                // B fragments (j = 0..3): one LDS.128 each
                unsigned bh[4][2], bl[4][2];
#pragma unroll
                for (int j = 0; j < 4; j++) {
                    int mr = warp_m * 32 + j * 8 + g4;
                    float4 p = *(const float4*)&sm.u.g.MS[mr][off];       // b0,b1 hi/lo
                    bh[j][0] = __float_as_uint(p.x); bl[j][0] = __float_as_uint(p.y);
                    bh[j][1] = __float_as_uint(p.z); bl[j][1] = __float_as_uint(p.w);
                }
#pragma unroll
                for (int i = 0; i < 2; i++)
#pragma unroll
                    for (int j = 0; j < 4; j++) {
                        mma_tf32(acc[i][j][0], acc[i][j][1], acc[i][j][2], acc[i][j][3],
                                 ah[i][0], ah[i][1], ah[i][2], ah[i][3], bh[j][0], bh[j][1]);
                        mma_tf32(acc[i][j][0], acc[i][j][1], acc[i][j][2], acc[i][j][3],
                                 ah[i][0], ah[i][1], ah[i][2], ah[i][3], bl[j][0], bl[j][1]);
                        mma_tf32(acc[i][j][0], acc[i][j][1], acc[i][j][2], acc[i][j][3],
                                 al[i][0], al[i][1], al[i][2], al[i][3], bh[j][0], bh[j][1]);
                    }
            }
            __syncthreads();
        }

        // ---- epilogue: args -> argbuf (union reuses tile smem) ----
#pragma unroll
        for (int i = 0; i < 2; i++)
#pragma unroll
            for (int r = 0; r < 2; r++) {
                int q = warp_q * 32 + i * 16 + r * 8 + g4;
                float xsi = xs[i][r], inv = inv1x[i][r];
#pragma unroll
                for (int j = 0; j < 4; j++) {
                    int ml = warp_m * 32 + j * 8 + 2 * tg;
                    float dA = acc[i][j][r * 2 + 0];
                    float dB = acc[i][j][r * 2 + 1];
                    float yA = sm.ys[ml], yB = sm.ys[ml + 1];
                    float d2A = fmaxf(xsi + yA - 2.f * dA, 0.f);
                    float d2B = fmaxf(xsi + yB - 2.f * dB, 0.f);
                    float argA = 1.f + 2.f * d2A / (inv * (1.f - yA) + 1e-8f);
                    float argB = 1.f + 2.f * d2B / (inv * (1.f - yB) + 1e-8f);
                    bool vA = (m0 + ml < mend), vB = (m0 + ml + 1 < mend);
                    float2 w = make_float2(vA ? argA : BIGF, vB ? argB : BIGF);
                    *(float2*)&sm.u.argbuf[q][ml] = w;
                }
            }
        __syncthreads();

        // ---- owner threads scan 64 candidates for their query ----
        if (tid < 128) {
            int q = tid;
#pragma unroll
            for (int c4 = 0; c4 < 16; c4++) {
                float4 v = *(const float4*)&sm.u.argbuf[q][c4 * 4];
                float av[4] = {v.x, v.y, v.z, v.w};
#pragma unroll
                for (int e = 0; e < 4; e++) {
                    float a = av[e];
                    if (a < worst) {
                        float mv = -1.f; int mp = 0;
#pragma unroll
                        for (int s = 0; s < KSEL; s++) {
                            float t = sm.s_ta[q][s];
                            if (t > mv) { mv = t; mp = s; }
                        }
                        sm.s_ta[q][mp] = a;
                        sm.s_ti[q][mp] = m0 + c4 * 4 + e;
                        mv = -1.f;
#pragma unroll
                        for (int s = 0; s < KSEL; s++) {
                            float t = sm.s_ta[q][s];
                            if (t > mv) mv = t;
                        }
                        worst = mv;
                    }
                }
            }
        }
        __syncthreads();
    }

    if (tid < 128) {
        int q = q0 + tid;
        int base = (q * NSPLIT + blockIdx.y) * KSEL;
#pragma unroll
        for (int s = 0; s < KSEL; s++) {
            g_cand_arg[base + s] = sm.s_ta[tid][s];
            g_cand_idx[base + s] = sm.s_ti[tid][s];
        }
    }
}

// ============================================================
// Kernel 3: merge candidates -> top-8, softmax, gather (unchanged)
// ============================================================
__global__ void merge_kernel(const float* __restrict__ masks, float* __restrict__ out)
{
    __shared__ float ca[NCAND];
    __shared__ int   ci[NCAND];
    __shared__ float sel_a[KSEL];
    __shared__ int   sel_i[KSEL];

    const int q = blockIdx.x;
    const int tid = threadIdx.x;

    for (int c = tid; c < NCAND; c += 256) {
        ca[c] = fmaxf(g_cand_arg[q * NCAND + c], 1.0f + 1e-6f);
        ci[c] = g_cand_idx[q * NCAND + c];
    }
    __syncthreads();

    for (int c = tid; c < NCAND; c += 256) {
        float a = ca[c];
        int idx = ci[c];
        int rank = 0;
        for (int o = 0; o < NCAND; o++) {
            float oa = ca[o];
            rank += (oa < a) || (oa == a && ci[o] < idx);
        }
        if (rank < KSEL) { sel_a[rank] = a; sel_i[rank] = idx; }
    }
    __syncthreads();

    if (tid == 0) {
        float d[KSEL];
#pragma unroll
        for (int s = 0; s < KSEL; s++) d[s] = acoshf(sel_a[s]);
        float d0 = d[0];
        float e[KSEL], sum = 0.f;
#pragma unroll
        for (int s = 0; s < KSEL; s++) { e[s] = expf(d0 - d[s]); sum += e[s]; }
        float inv = 1.0f / sum;
#pragma unroll
        for (int s = 0; s < KSEL; s++) out[q * KSEL + s] = e[s] * inv;
    }
    __syncthreads();

    float* hout = out + (size_t)BQ * KSEL;
    for (int e = tid; e < KSEL * MAXA; e += 256) {
        int s = e / MAXA, a = e - s * MAXA;
        hout[((size_t)q * KSEL + s) * MAXA + a] = masks[(size_t)sel_i[s] * MAXA + a];
    }
}

// ============================================================
extern "C" void kernel_launch(void* const* d_in, const int* in_sizes, int n_in,
                              void* d_out, int out_size)
{
    (void)in_sizes; (void)n_in; (void)out_size;
    const float* q_emb  = (const float*)d_in[0];
    const float* m_emb  = (const float*)d_in[1];
    const float* masks  = (const float*)d_in[2];
    const float* W      = (const float*)d_in[3];
    const float* bias   = (const float*)d_in[4];
    float* out = (float*)d_out;

    float *d_mh, *d_msq, *d_qh, *d_qsq;
    cudaGetSymbolAddress((void**)&d_mh,  g_mem_hyp);
    cudaGetSymbolAddress((void**)&d_msq, g_mem_sq);
    cudaGetSymbolAddress((void**)&d_qh,  g_q_hyp);
    cudaGetSymbolAddress((void**)&d_qsq, g_q_sq);

    transform_kernel<<<(NM + 63) / 64, 256>>>(m_emb, W, bias, d_mh, d_msq, NM);
    transform_kernel<<<(BQ + 63) / 64, 256>>>(q_emb, W, bias, d_qh, d_qsq, BQ);

    dim3 g2(BQ / 128, NSPLIT);
    dist_topk_kernel<<<g2, 256>>>();

    merge_kernel<<<BQ, 256>>>(masks, out);
}

// round 7
// speedup vs baseline: 1.7904x; 1.7904x over previous
#include <cuda_runtime.h>
#include <cuda_bf16.h>
#include <math.h>
#include <stdint.h>

#define BQ    1024
#define NM    50000
#define DD    256
#define MAXA  200
#define KSEL  8
#define NSPLIT 37
#define SPLEN  1352            // ceil(50000/37)
#define NCAND (NSPLIT*KSEL)    // 296
#define BIGF  3.0e38f

// -------- device scratch --------
__device__ unsigned g_mem_hi[NM * 128];   // bf16x2: col pair per u32
__device__ unsigned g_mem_lo[NM * 128];
__device__ unsigned g_q_hi[BQ * 128];
__device__ unsigned g_q_lo[BQ * 128];
__device__ float    g_mem_sq[NM];
__device__ float    g_q_sq[BQ];
__device__ float    g_cand_arg[BQ * NCAND];
__device__ int      g_cand_idx[BQ * NCAND];

// ===================== PTX helpers =====================
__device__ __forceinline__ uint32_t smem_u32(const void* p) {
    uint32_t a;
    asm("{ .reg .u64 t; cvta.to.shared.u64 t, %1; cvt.u32.u64 %0, t; }" : "=r"(a) : "l"(p));
    return a;
}
#define LDSM_X4(r0, r1, r2, r3, addr) \
    asm volatile("ldmatrix.sync.aligned.m8n8.x4.shared.b16 {%0,%1,%2,%3}, [%4];" \
        : "=r"(r0), "=r"(r1), "=r"(r2), "=r"(r3) : "r"(addr))

__device__ __forceinline__ void mma_bf16(float* c, const uint32_t* a,
                                         uint32_t b0, uint32_t b1) {
    asm volatile("mma.sync.aligned.m16n8k16.row.col.f32.bf16.bf16.f32 "
        "{%0,%1,%2,%3},{%4,%5,%6,%7},{%8,%9},{%0,%1,%2,%3};"
        : "+f"(c[0]), "+f"(c[1]), "+f"(c[2]), "+f"(c[3])
        : "r"(a[0]), "r"(a[1]), "r"(a[2]), "r"(a[3]), "r"(b0), "r"(b1));
}

// -------- packed f32x2 helpers (transform kernel) --------
__device__ __forceinline__ unsigned long long dup2(float x) {
    unsigned long long r;
    asm("mov.b64 %0, {%1, %1};" : "=l"(r) : "f"(x));
    return r;
}
__device__ __forceinline__ void ffma2(unsigned long long& d,
                                      unsigned long long a, unsigned long long b) {
    asm("fma.rn.f32x2 %0, %1, %2, %0;" : "+l"(d) : "l"(a), "l"(b));
}
__device__ __forceinline__ float2 unpack2(unsigned long long v) {
    float2 r;
    asm("mov.b64 {%0, %1}, %2;" : "=f"(r.x), "=f"(r.y) : "l"(v));
    return r;
}

// ============================================================
// Kernel 1: H = tanh(X@W+b), Poincare rescale, |h|^2, bf16 hi/lo split out.
// ============================================================
__global__ __launch_bounds__(256, 2)
void transform_kernel(const float* __restrict__ X, const float* __restrict__ W,
                      const float* __restrict__ bias,
                      unsigned* __restrict__ Hhi, unsigned* __restrict__ Hlo,
                      float* __restrict__ SQ, int M)
{
    __shared__ float  Xs[64][17];
    __shared__ float2 Ws2[16][128];
    __shared__ float  s_scale[64];

    const int tid = threadIdx.x;
    const int tx = tid & 15, ty = tid >> 4;
    const int row0 = blockIdx.x * 64;

    unsigned long long acc2[4][8];
#pragma unroll
    for (int i = 0; i < 4; i++)
#pragma unroll
        for (int j = 0; j < 8; j++) acc2[i][j] = 0ull;

    for (int kc = 0; kc < DD; kc += 16) {
#pragma unroll
        for (int e = tid; e < 64 * 16; e += 256) {
            int r = e >> 4, k = e & 15;
            float v = 0.f;
            if (row0 + r < M) v = X[(row0 + r) * DD + kc + k];
            Xs[r][k] = v;
        }
#pragma unroll
        for (int e = tid; e < 16 * 256; e += 256) {
            int k = e >> 8, c = e & 255;
            ((float*)Ws2)[k * 256 + c] = W[(kc + k) * DD + c];
        }
        __syncthreads();
#pragma unroll
        for (int k = 0; k < 16; k++) {
            unsigned long long a2[4], b2[8];
#pragma unroll
            for (int i = 0; i < 4; i++) a2[i] = dup2(Xs[ty + 16 * i][k]);
#pragma unroll
            for (int j = 0; j < 8; j++) {
                float2 bv = Ws2[k][tx + 16 * j];
                b2[j] = *(unsigned long long*)&bv;
            }
#pragma unroll
            for (int i = 0; i < 4; i++)
#pragma unroll
                for (int j = 0; j < 8; j++)
                    ffma2(acc2[i][j], a2[i], b2[j]);
        }
        __syncthreads();
    }

    const float2* bias2 = (const float2*)bias;
    float2 hv[4][8];
    float psum[4];
#pragma unroll
    for (int i = 0; i < 4; i++) {
        psum[i] = 0.f;
#pragma unroll
        for (int j = 0; j < 8; j++) {
            float2 bb = bias2[tx + 16 * j];
            float2 v = unpack2(acc2[i][j]);
            v.x = tanhf(v.x + bb.x);
            v.y = tanhf(v.y + bb.y);
            hv[i][j] = v;
            psum[i] += v.x * v.x + v.y * v.y;
        }
    }
#pragma unroll
    for (int off = 1; off < 16; off <<= 1) {
#pragma unroll
        for (int i = 0; i < 4; i++)
            psum[i] += __shfl_xor_sync(0xffffffffu, psum[i], off);
    }
    if (tx == 0) {
#pragma unroll
        for (int i = 0; i < 4; i++) {
            int r = ty + 16 * i;
            float norm = sqrtf(psum[i]);
            float sc = (norm > 0.95f) ? 0.95f / norm : 1.0f;
            s_scale[r] = sc;
            if (row0 + r < M) SQ[row0 + r] = psum[i] * sc * sc;
        }
    }
    __syncthreads();
#pragma unroll
    for (int i = 0; i < 4; i++) {
        int r = ty + 16 * i;
        if (row0 + r >= M) continue;
        float sc = s_scale[r];
#pragma unroll
        for (int j = 0; j < 8; j++) {
            float2 v = hv[i][j];
            v.x *= sc; v.y *= sc;
            __nv_bfloat16 hx = __float2bfloat16(v.x);
            __nv_bfloat16 hy = __float2bfloat16(v.y);
            __nv_bfloat16 lx = __float2bfloat16(v.x - __bfloat162float(hx));
            __nv_bfloat16 ly = __float2bfloat16(v.y - __bfloat162float(hy));
            size_t o = (size_t)(row0 + r) * 128 + tx + 16 * j;
            Hhi[o] = ((unsigned)__bfloat16_as_ushort(hy) << 16) | __bfloat16_as_ushort(hx);
            Hlo[o] = ((unsigned)__bfloat16_as_ushort(ly) << 16) | __bfloat16_as_ushort(lx);
        }
    }
}

// ============================================================
// Kernel 2: bf16 mma.sync m16n8k16 3-term split GEMM + arg + top-8/split.
// CTA 128q x 64m, 8 warps (warp = 32q x 32m), BK=64 (4 k16 steps per fill).
// smem tiles: row stride 144B (16B aligned, odd*16 -> conflict-free ldmatrix).
// ============================================================
#define RS       144                  // bytes per tile row
#define QTILE_B  (128 * RS)           // 18432
#define MTILE_B  (64 * RS)            // 9216
#define OFF_QH   0
#define OFF_QL   (QTILE_B)            // 18432
#define OFF_MH   (2 * QTILE_B)        // 36864
#define OFF_ML   (2 * QTILE_B + MTILE_B)  // 46080
#define OFF_YS   (2 * QTILE_B + 2 * MTILE_B)  // 55296
#define OFF_TA   (OFF_YS + 256)       // 55552
#define OFF_TI   (OFF_TA + 4096)      // 59648
#define DSMEM_SZ (OFF_TI + 4096)      // 63744
#define ABROW    72                   // argbuf floats per row (union over QH/QL)

__device__ __forceinline__ void fill_q(char* dst, const uint4* src,
                                       int q0, int kc8, int tid) {
#pragma unroll
    for (int it = 0; it < 4; it++) {
        int idx = tid + 256 * it;           // 1024 uint4
        int r = idx >> 3, kb = idx & 7;
        uint4 v = src[(size_t)(q0 + r) * 32 + kc8 + kb];
        *(uint4*)(dst + r * RS + kb * 16) = v;
    }
}
__device__ __forceinline__ void fill_m(char* dst, const uint4* src,
                                       int m0, int kc8, int mend, int tid) {
#pragma unroll
    for (int it = 0; it < 2; it++) {
        int idx = tid + 256 * it;           // 512 uint4
        int r = idx >> 3, kb = idx & 7;
        uint4 v = make_uint4(0u, 0u, 0u, 0u);
        if (m0 + r < mend) v = src[(size_t)(m0 + r) * 32 + kc8 + kb];
        *(uint4*)(dst + r * RS + kb * 16) = v;
    }
}

__device__ __forceinline__ void top8_insert(float* ta, int* ti, float a, int m,
                                            float& worst) {
    float mv = -1.f; int mp = 0;
#pragma unroll
    for (int s = 0; s < KSEL; s++) {
        float v = ta[s];
        if (v > mv) { mv = v; mp = s; }
    }
    ta[mp] = a; ti[mp] = m;
    mv = -1.f;
#pragma unroll
    for (int s = 0; s < KSEL; s++) {
        float v = ta[s];
        if (v > mv) mv = v;
    }
    worst = mv;
}

__global__ __launch_bounds__(256, 2)
void dist_topk_kernel()
{
    extern __shared__ char sb[];
    const uint32_t sbase = smem_u32(sb);

    float* tYS = (float*)(sb + OFF_YS);
    float* ta_all = (float*)(sb + OFF_TA);
    int*   ti_all = (int*)(sb + OFF_TI);
    float* argbuf = (float*)(sb + OFF_QH);     // union over QH/QL after mma

    const int tid = threadIdx.x;
    const int lane = tid & 31;
    const int wid = tid >> 5;
    const int warp_q = wid & 3;
    const int warp_m = wid >> 2;
    const int g4 = lane >> 2;
    const int tg = lane & 3;

    const int q0 = blockIdx.x * 128;
    const int mstart = blockIdx.y * SPLEN;
    const int mend = min(mstart + SPLEN, NM);

    // ldmatrix lane addresses (within tile, byte offsets)
    const uint32_t aOff = (uint32_t)((warp_q * 32 + (lane & 7) + ((lane >> 3) & 1) * 8) * RS
                                     + (((lane >> 4) & 1) * 8) * 2);
    const uint32_t bOff = (uint32_t)((warp_m * 32 + (lane & 7) + ((lane >> 4) & 1) * 8) * RS
                                     + (((lane >> 3) & 1) * 8) * 2);
    const uint32_t u_qh = sbase + OFF_QH;
    const uint32_t u_mh = sbase + OFF_MH;

    float xs[2][2], inv1x[2][2];
#pragma unroll
    for (int i = 0; i < 2; i++)
#pragma unroll
        for (int r = 0; r < 2; r++) {
            float v = g_q_sq[q0 + warp_q * 32 + i * 16 + r * 8 + g4];
            xs[i][r] = v;
            inv1x[i][r] = 1.0f - v;
        }

    if (tid < 128) {
        float* ta = ta_all + tid * KSEL;
        int* ti = ti_all + tid * KSEL;
#pragma unroll
        for (int s = 0; s < KSEL; s++) { ta[s] = BIGF; ti[s] = 0x7fffffff; }
    }
    float worst = BIGF;
    __syncthreads();

    const uint4* pQH = (const uint4*)g_q_hi;
    const uint4* pQL = (const uint4*)g_q_lo;
    const uint4* pMH = (const uint4*)g_mem_hi;
    const uint4* pML = (const uint4*)g_mem_lo;

    for (int m0 = mstart; m0 < mend; m0 += 64) {
        if (tid < 64) tYS[tid] = (m0 + tid < mend) ? g_mem_sq[m0 + tid] : 0.f;

        float acc[2][4][4];
#pragma unroll
        for (int i = 0; i < 2; i++)
#pragma unroll
            for (int j = 0; j < 4; j++)
#pragma unroll
                for (int c = 0; c < 4; c++) acc[i][j][c] = 0.f;

        for (int kc8 = 0; kc8 < 32; kc8 += 8) {      // 4 chunks of BK=64 bf16
            fill_q(sb + OFF_QH, pQH, q0, kc8, tid);
            fill_q(sb + OFF_QL, pQL, q0, kc8, tid);
            fill_m(sb + OFF_MH, pMH, m0, kc8, mend, tid);
            fill_m(sb + OFF_ML, pML, m0, kc8, mend, tid);
            __syncthreads();

#pragma unroll
            for (int ks = 0; ks < 4; ks++) {
                uint32_t ah[2][4], al[2][4], bh[2][4], bl[2][4];
                const uint32_t aA = u_qh + aOff + ks * 32;
#pragma unroll
                for (int i = 0; i < 2; i++) {
                    LDSM_X4(ah[i][0], ah[i][1], ah[i][2], ah[i][3], aA + i * (16 * RS));
                    LDSM_X4(al[i][0], al[i][1], al[i][2], al[i][3],
                            aA + i * (16 * RS) + QTILE_B);
                }
                const uint32_t bA = u_mh + bOff + ks * 32;
#pragma unroll
                for (int jj = 0; jj < 2; jj++) {
                    LDSM_X4(bh[jj][0], bh[jj][1], bh[jj][2], bh[jj][3],
                            bA + jj * (16 * RS));
                    LDSM_X4(bl[jj][0], bl[jj][1], bl[jj][2], bl[jj][3],
                            bA + jj * (16 * RS) + MTILE_B);
                }
#pragma unroll
                for (int i = 0; i < 2; i++)
#pragma unroll
                    for (int j = 0; j < 4; j++) {
                        int jj = j >> 1, s = (j & 1) * 2;
                        mma_bf16(acc[i][j], ah[i], bh[jj][s], bh[jj][s + 1]);
                        mma_bf16(acc[i][j], ah[i], bl[jj][s], bl[jj][s + 1]);
                        mma_bf16(acc[i][j], al[i], bh[jj][s], bh[jj][s + 1]);
                    }
            }
            __syncthreads();
        }

        // ---- epilogue: args -> argbuf (reuses tile smem; safe after sync) ----
#pragma unroll
        for (int i = 0; i < 2; i++)
#pragma unroll
            for (int r = 0; r < 2; r++) {
                int q = warp_q * 32 + i * 16 + r * 8 + g4;
                float xsi = xs[i][r], inv = inv1x[i][r];
#pragma unroll
                for (int j = 0; j < 4; j++) {
                    int ml = warp_m * 32 + j * 8 + 2 * tg;
                    float dA = acc[i][j][r * 2 + 0];
                    float dB = acc[i][j][r * 2 + 1];
                    float yA = tYS[ml], yB = tYS[ml + 1];
                    float d2A = fmaxf(xsi + yA - 2.f * dA, 0.f);
                    float d2B = fmaxf(xsi + yB - 2.f * dB, 0.f);
                    float argA = 1.f + 2.f * d2A / (inv * (1.f - yA) + 1e-8f);
                    float argB = 1.f + 2.f * d2B / (inv * (1.f - yB) + 1e-8f);
                    bool vA = (m0 + ml < mend), vB = (m0 + ml + 1 < mend);
                    float2 w = make_float2(vA ? argA : BIGF, vB ? argB : BIGF);
                    *(float2*)&argbuf[q * ABROW + ml] = w;
                }
            }
        __syncthreads();

        if (tid < 128) {
            int q = tid;
            float* ta = ta_all + q * KSEL;
            int* ti = ti_all + q * KSEL;
#pragma unroll
            for (int c4 = 0; c4 < 16; c4++) {
                float4 v = *(const float4*)&argbuf[q * ABROW + c4 * 4];
                float av[4] = {v.x, v.y, v.z, v.w};
#pragma unroll
                for (int e = 0; e < 4; e++) {
                    float a = av[e];
                    if (a < worst)
                        top8_insert(ta, ti, a, m0 + c4 * 4 + e, worst);
                }
            }
        }
        __syncthreads();
    }

    if (tid < 128) {
        int base = ((q0 + tid) * NSPLIT + blockIdx.y) * KSEL;
        float* ta = ta_all + tid * KSEL;
        int* ti = ti_all + tid * KSEL;
#pragma unroll
        for (int s = 0; s < KSEL; s++) {
            g_cand_arg[base + s] = ta[s];
            g_cand_idx[base + s] = ti[s];
        }
    }
}

// ============================================================
// Kernel 3: merge 296 candidates -> top-8 via 8-round argmin
// (lexicographic (arg, idx), matching jax.lax.top_k tie semantics).
// ============================================================
__global__ void merge_kernel(const float* __restrict__ masks, float* __restrict__ out)
{
    __shared__ float ca[NCAND];
    __shared__ int   ci[NCAND];
    __shared__ float wa[8];
    __shared__ int   wi[8], wp[8];
    __shared__ float sel_a[KSEL];
    __shared__ int   sel_i[KSEL];

    const int q = blockIdx.x;
    const int tid = threadIdx.x;
    const int lane = tid & 31, wid = tid >> 5;

    for (int c = tid; c < NCAND; c += 256) {
        ca[c] = fmaxf(g_cand_arg[q * NCAND + c], 1.0f + 1e-6f);
        ci[c] = g_cand_idx[q * NCAND + c];
    }
    __syncthreads();

    for (int r = 0; r < KSEL; r++) {
        float ba = BIGF; int bi = 0x7fffffff, bp = 0;
        for (int c = tid; c < NCAND; c += 256) {
            float a = ca[c]; int i = ci[c];
            if (a < ba || (a == ba && i < bi)) { ba = a; bi = i; bp = c; }
        }
#pragma unroll
        for (int off = 16; off; off >>= 1) {
            float oa = __shfl_down_sync(0xffffffffu, ba, off);
            int oi = __shfl_down_sync(0xffffffffu, bi, off);
            int op = __shfl_down_sync(0xffffffffu, bp, off);
            if (oa < ba || (oa == ba && oi < bi)) { ba = oa; bi = oi; bp = op; }
        }
        if (lane == 0) { wa[wid] = ba; wi[wid] = bi; wp[wid] = bp; }
        __syncthreads();
        if (tid == 0) {
            float fa = wa[0]; int fi = wi[0], fp = wp[0];
#pragma unroll
            for (int w = 1; w < 8; w++) {
                if (wa[w] < fa || (wa[w] == fa && wi[w] < fi)) {
                    fa = wa[w]; fi = wi[w]; fp = wp[w];
                }
            }
            sel_a[r] = fa; sel_i[r] = fi;
            ca[fp] = BIGF;
        }
        __syncthreads();
    }

    if (tid == 0) {
        float d[KSEL];
#pragma unroll
        for (int s = 0; s < KSEL; s++) d[s] = acoshf(sel_a[s]);
        float d0 = d[0];
        float e[KSEL], sum = 0.f;
#pragma unroll
        for (int s = 0; s < KSEL; s++) { e[s] = expf(d0 - d[s]); sum += e[s]; }
        float inv = 1.0f / sum;
#pragma unroll
        for (int s = 0; s < KSEL; s++) out[q * KSEL + s] = e[s] * inv;
    }
    __syncthreads();

    float4* hout = (float4*)(out + (size_t)BQ * KSEL);
    for (int e = tid; e < KSEL * (MAXA / 4); e += 256) {
        int s = e / (MAXA / 4), a4 = e - s * (MAXA / 4);
        const float4* src = (const float4*)(masks + (size_t)sel_i[s] * MAXA);
        hout[((size_t)q * KSEL + s) * (MAXA / 4) + a4] = src[a4];
    }
}

// ============================================================
extern "C" void kernel_launch(void* const* d_in, const int* in_sizes, int n_in,
                              void* d_out, int out_size)
{
    (void)in_sizes; (void)n_in; (void)out_size;
    const float* q_emb  = (const float*)d_in[0];
    const float* m_emb  = (const float*)d_in[1];
    const float* masks  = (const float*)d_in[2];
    const float* W      = (const float*)d_in[3];
    const float* bias   = (const float*)d_in[4];
    float* out = (float*)d_out;

    unsigned *d_mhi, *d_mlo, *d_qhi, *d_qlo;
    float *d_msq, *d_qsq;
    cudaGetSymbolAddress((void**)&d_mhi, g_mem_hi);
    cudaGetSymbolAddress((void**)&d_mlo, g_mem_lo);
    cudaGetSymbolAddress((void**)&d_qhi, g_q_hi);
    cudaGetSymbolAddress((void**)&d_qlo, g_q_lo);
    cudaGetSymbolAddress((void**)&d_msq, g_mem_sq);
    cudaGetSymbolAddress((void**)&d_qsq, g_q_sq);

    cudaFuncSetAttribute(dist_topk_kernel,
                         cudaFuncAttributeMaxDynamicSharedMemorySize, DSMEM_SZ);

    transform_kernel<<<(NM + 63) / 64, 256>>>(m_emb, W, bias, d_mhi, d_mlo, d_msq, NM);
    transform_kernel<<<(BQ + 63) / 64, 256>>>(q_emb, W, bias, d_qhi, d_qlo, d_qsq, BQ);

    dim3 g2(BQ / 128, NSPLIT);
    dist_topk_kernel<<<g2, 256, DSMEM_SZ>>>();

    merge_kernel<<<BQ, 256>>>(masks, out);
}